// round 1
// baseline (speedup 1.0000x reference)
#include <cuda_runtime.h>
#include <cuda_bf16.h>
#include <math_constants.h>

// Problem constants
#define BATCH 4
#define SEQ   1536
#define DIM   2048
#define NHEAD 16
#define HD    128            // head dim
#define ROWS  (BATCH*SEQ)    // 6144
#define QKVN  (3*DIM)        // 6144

// Scratch (device globals: allocation-free rule)
__device__ float g_qkv[(size_t)ROWS * QKVN];   // [6144, 6144]  ~151MB
__device__ float g_attn[(size_t)ROWS * DIM];   // [6144, 2048]  ~50MB

// ---------------------------------------------------------------------------
// SGEMM: C[M,N] = A[M,K] @ B[K,N] + bias[N]
// 128x128 tile, K-step 16, 256 threads, 8x8 per thread.
// ---------------------------------------------------------------------------
__global__ __launch_bounds__(256) void sgemm_bias_kernel(
    const float* __restrict__ A, const float* __restrict__ B,
    const float* __restrict__ bias, float* __restrict__ C,
    int M, int N, int K)
{
    __shared__ float As[16][128];   // transposed: As[k][m]
    __shared__ float Bs[16][128];   // Bs[k][n]

    const int tid = threadIdx.x;
    const int tx = tid & 15;        // 0..15  -> col group
    const int ty = tid >> 4;        // 0..15  -> row group
    const int row0 = blockIdx.y * 128;
    const int col0 = blockIdx.x * 128;

    // A load mapping: 128 rows x 16 cols, 8 floats/thread
    const int a_row = tid >> 1;          // 0..127
    const int a_col = (tid & 1) * 8;     // 0 or 8
    // B load mapping: 16 rows x 128 cols, 8 floats/thread
    const int b_row = tid >> 4;          // 0..15
    const int b_col = (tid & 15) * 8;

    float acc[8][8];
    #pragma unroll
    for (int i = 0; i < 8; i++)
        #pragma unroll
        for (int j = 0; j < 8; j++) acc[i][j] = 0.0f;

    const float* Aptr = A + (size_t)(row0 + a_row) * K + a_col;
    const float* Bptr = B + (size_t)b_row * N + col0 + b_col;

    for (int k0 = 0; k0 < K; k0 += 16) {
        float4 av0 = *(const float4*)(Aptr + k0);
        float4 av1 = *(const float4*)(Aptr + k0 + 4);
        As[a_col + 0][a_row] = av0.x;
        As[a_col + 1][a_row] = av0.y;
        As[a_col + 2][a_row] = av0.z;
        As[a_col + 3][a_row] = av0.w;
        As[a_col + 4][a_row] = av1.x;
        As[a_col + 5][a_row] = av1.y;
        As[a_col + 6][a_row] = av1.z;
        As[a_col + 7][a_row] = av1.w;

        float4 bv0 = *(const float4*)(Bptr + (size_t)k0 * N);
        float4 bv1 = *(const float4*)(Bptr + (size_t)k0 * N + 4);
        *(float4*)&Bs[b_row][b_col]     = bv0;
        *(float4*)&Bs[b_row][b_col + 4] = bv1;

        __syncthreads();

        #pragma unroll
        for (int kk = 0; kk < 16; kk++) {
            float ar[8], br[8];
            *(float4*)(ar)     = *(const float4*)&As[kk][ty * 8];
            *(float4*)(ar + 4) = *(const float4*)&As[kk][ty * 8 + 4];
            *(float4*)(br)     = *(const float4*)&Bs[kk][tx * 8];
            *(float4*)(br + 4) = *(const float4*)&Bs[kk][tx * 8 + 4];
            #pragma unroll
            for (int i = 0; i < 8; i++)
                #pragma unroll
                for (int j = 0; j < 8; j++)
                    acc[i][j] = fmaf(ar[i], br[j], acc[i][j]);
        }
        __syncthreads();
    }

    // epilogue: + bias, float4 stores
    #pragma unroll
    for (int i = 0; i < 8; i++) {
        const int row = row0 + ty * 8 + i;
        float* cptr = C + (size_t)row * N + col0 + tx * 8;
        const float* bptr = bias + col0 + tx * 8;
        float4 o0, o1;
        o0.x = acc[i][0] + bptr[0];
        o0.y = acc[i][1] + bptr[1];
        o0.z = acc[i][2] + bptr[2];
        o0.w = acc[i][3] + bptr[3];
        o1.x = acc[i][4] + bptr[4];
        o1.y = acc[i][5] + bptr[5];
        o1.z = acc[i][6] + bptr[6];
        o1.w = acc[i][7] + bptr[7];
        *(float4*)(cptr)     = o0;
        *(float4*)(cptr + 4) = o1;
    }
}

// ---------------------------------------------------------------------------
// RMSNorm over hidden dim (2048), in place on the q (y=0) / k (y=1) thirds.
// ---------------------------------------------------------------------------
__global__ __launch_bounds__(256) void rmsnorm_kernel(
    float* __restrict__ qkv, const float* __restrict__ qw, const float* __restrict__ kw)
{
    const int row   = blockIdx.x;     // 0..6143
    const int which = blockIdx.y;     // 0 = q, 1 = k
    float* p = qkv + (size_t)row * QKVN + which * DIM;
    const float* w = which ? kw : qw;
    const int tid = threadIdx.x;

    float4 v0 = *(const float4*)(p + tid * 8);
    float4 v1 = *(const float4*)(p + tid * 8 + 4);
    float ss = v0.x*v0.x + v0.y*v0.y + v0.z*v0.z + v0.w*v0.w
             + v1.x*v1.x + v1.y*v1.y + v1.z*v1.z + v1.w*v1.w;

    // warp reduce then block reduce
    #pragma unroll
    for (int off = 16; off > 0; off >>= 1)
        ss += __shfl_xor_sync(0xffffffffu, ss, off);

    __shared__ float warpsum[8];
    __shared__ float s_rn;
    if ((tid & 31) == 0) warpsum[tid >> 5] = ss;
    __syncthreads();
    if (tid == 0) {
        float tot = 0.f;
        #pragma unroll
        for (int i = 0; i < 8; i++) tot += warpsum[i];
        s_rn = rsqrtf(tot * (1.0f / DIM) + 1e-6f);
    }
    __syncthreads();
    const float rn = s_rn;

    const float* wp = w + tid * 8;
    float4 w0 = *(const float4*)(wp);
    float4 w1 = *(const float4*)(wp + 4);
    v0.x *= rn * w0.x; v0.y *= rn * w0.y; v0.z *= rn * w0.z; v0.w *= rn * w0.w;
    v1.x *= rn * w1.x; v1.y *= rn * w1.y; v1.z *= rn * w1.z; v1.w *= rn * w1.w;
    *(float4*)(p + tid * 8)     = v0;
    *(float4*)(p + tid * 8 + 4) = v1;
}

// ---------------------------------------------------------------------------
// Flash-style causal attention.
// Grid: (SEQ/64, BATCH*NHEAD). 256 threads (16x16). BM=BN=64, HD=128.
// smem: Qt[128][64] Kt[128][64] Vs[64][128] Pt[64][64]  = 114688 B dynamic.
// Thread (tx,ty): score micro-tile 4x4 at rows ty*4.., cols tx*4..
//                 O micro-tile 4x8  at rows ty*4.., cols tx*8..
// ---------------------------------------------------------------------------
__global__ __launch_bounds__(256) void attn_kernel(
    const float* __restrict__ qkv, float* __restrict__ out)
{
    extern __shared__ float sm[];
    float* Qt = sm;                  // [128][64]
    float* Kt = sm + 128 * 64;       // [128][64]
    float* Vs = sm + 2 * 128 * 64;   // [64][128]
    float* Pt = sm + 3 * 128 * 64;   // [64][64]

    const int qtile = blockIdx.x;          // 0..23
    const int bh    = blockIdx.y;          // 0..63
    const int b = bh >> 4;
    const int h = bh & 15;
    const int tid = threadIdx.x;
    const int tx = tid & 15;
    const int ty = tid >> 4;

    const size_t rowstride = QKVN;  // 6144
    const float* qbase = qkv + (size_t)b * SEQ * rowstride + h * HD;
    const float* kbase = qbase + DIM;
    const float* vbase = qbase + 2 * DIM;

    // load Q tile transposed: Qt[d][r]
    {
        const int r  = tid >> 2;           // 0..63
        const int c0 = (tid & 3) * 32;     // 0,32,64,96
        const float* src = qbase + (size_t)(qtile * 64 + r) * rowstride + c0;
        #pragma unroll
        for (int c = 0; c < 32; c += 4) {
            float4 v = *(const float4*)(src + c);
            Qt[(c0 + c + 0) * 64 + r] = v.x;
            Qt[(c0 + c + 1) * 64 + r] = v.y;
            Qt[(c0 + c + 2) * 64 + r] = v.z;
            Qt[(c0 + c + 3) * 64 + r] = v.w;
        }
    }

    float o[4][8];
    #pragma unroll
    for (int i = 0; i < 4; i++)
        #pragma unroll
        for (int c = 0; c < 8; c++) o[i][c] = 0.0f;
    float m_i[4] = {-CUDART_INF_F, -CUDART_INF_F, -CUDART_INF_F, -CUDART_INF_F};
    float l_i[4] = {0.f, 0.f, 0.f, 0.f};

    const float scale = 0.08838834764831845f;  // 1/sqrt(128)

    for (int kt = 0; kt <= qtile; kt++) {
        __syncthreads();   // protect Kt/Vs/Pt reuse (also orders Qt on first iter)
        // load K tile transposed + V tile row-major
        {
            const int r  = tid >> 2;
            const int c0 = (tid & 3) * 32;
            const size_t krow = (size_t)(kt * 64 + r);
            const float* ksrc = kbase + krow * rowstride + c0;
            const float* vsrc = vbase + krow * rowstride + c0;
            #pragma unroll
            for (int c = 0; c < 32; c += 4) {
                float4 kv = *(const float4*)(ksrc + c);
                Kt[(c0 + c + 0) * 64 + r] = kv.x;
                Kt[(c0 + c + 1) * 64 + r] = kv.y;
                Kt[(c0 + c + 2) * 64 + r] = kv.z;
                Kt[(c0 + c + 3) * 64 + r] = kv.w;
                *(float4*)&Vs[r * 128 + c0 + c] = *(const float4*)(vsrc + c);
            }
        }
        __syncthreads();

        // scores s[4][4] = Q K^T
        float s[4][4];
        #pragma unroll
        for (int i = 0; i < 4; i++)
            #pragma unroll
            for (int j = 0; j < 4; j++) s[i][j] = 0.0f;

        for (int kk = 0; kk < 128; kk++) {
            float4 qv = *(const float4*)&Qt[kk * 64 + ty * 4];
            float4 kv = *(const float4*)&Kt[kk * 64 + tx * 4];
            float qr[4] = {qv.x, qv.y, qv.z, qv.w};
            float kr[4] = {kv.x, kv.y, kv.z, kv.w};
            #pragma unroll
            for (int i = 0; i < 4; i++)
                #pragma unroll
                for (int j = 0; j < 4; j++)
                    s[i][j] = fmaf(qr[i], kr[j], s[i][j]);
        }

        // scale + causal mask (only needed on diagonal tile)
        if (kt == qtile) {
            #pragma unroll
            for (int i = 0; i < 4; i++)
                #pragma unroll
                for (int j = 0; j < 4; j++) {
                    const int qr = ty * 4 + i, kr = tx * 4 + j;
                    s[i][j] = (kr > qr) ? -1e30f : s[i][j] * scale;
                }
        } else {
            #pragma unroll
            for (int i = 0; i < 4; i++)
                #pragma unroll
                for (int j = 0; j < 4; j++) s[i][j] *= scale;
        }

        // online softmax per row (rows owned by the 16 lanes sharing ty)
        float p[4][4];
        #pragma unroll
        for (int i = 0; i < 4; i++) {
            float rm = fmaxf(fmaxf(s[i][0], s[i][1]), fmaxf(s[i][2], s[i][3]));
            #pragma unroll
            for (int off = 1; off < 16; off <<= 1)
                rm = fmaxf(rm, __shfl_xor_sync(0xffffffffu, rm, off));
            const float mnew = fmaxf(m_i[i], rm);
            const float corr = __expf(m_i[i] - mnew);
            m_i[i] = mnew;
            float sum = 0.f;
            #pragma unroll
            for (int j = 0; j < 4; j++) {
                p[i][j] = __expf(s[i][j] - mnew);
                sum += p[i][j];
            }
            #pragma unroll
            for (int off = 1; off < 16; off <<= 1)
                sum += __shfl_xor_sync(0xffffffffu, sum, off);
            l_i[i] = l_i[i] * corr + sum;
            #pragma unroll
            for (int c = 0; c < 8; c++) o[i][c] *= corr;
        }

        // write P transposed: Pt[kcol][qrow]
        #pragma unroll
        for (int j = 0; j < 4; j++)
            #pragma unroll
            for (int i = 0; i < 4; i++)
                Pt[(tx * 4 + j) * 64 + ty * 4 + i] = p[i][j];
        __syncthreads();

        // O += P @ V
        for (int kk = 0; kk < 64; kk++) {
            float4 pv = *(const float4*)&Pt[kk * 64 + ty * 4];
            float4 v0 = *(const float4*)&Vs[kk * 128 + tx * 8];
            float4 v1 = *(const float4*)&Vs[kk * 128 + tx * 8 + 4];
            float pr[4] = {pv.x, pv.y, pv.z, pv.w};
            float vr[8] = {v0.x, v0.y, v0.z, v0.w, v1.x, v1.y, v1.z, v1.w};
            #pragma unroll
            for (int i = 0; i < 4; i++)
                #pragma unroll
                for (int c = 0; c < 8; c++)
                    o[i][c] = fmaf(pr[i], vr[c], o[i][c]);
        }
    }

    // epilogue: divide by l, write [B,S,H*hd]
    #pragma unroll
    for (int i = 0; i < 4; i++) {
        const float inv = 1.0f / l_i[i];
        const int q = qtile * 64 + ty * 4 + i;
        float* dst = out + ((size_t)b * SEQ + q) * DIM + h * HD + tx * 8;
        float4 o0, o1;
        o0.x = o[i][0] * inv; o0.y = o[i][1] * inv; o0.z = o[i][2] * inv; o0.w = o[i][3] * inv;
        o1.x = o[i][4] * inv; o1.y = o[i][5] * inv; o1.z = o[i][6] * inv; o1.w = o[i][7] * inv;
        *(float4*)(dst)     = o0;
        *(float4*)(dst + 4) = o1;
    }
}

// ---------------------------------------------------------------------------
extern "C" void kernel_launch(void* const* d_in, const int* in_sizes, int n_in,
                              void* d_out, int out_size)
{
    const float* x      = (const float*)d_in[0];
    const float* w_qkv  = (const float*)d_in[1];
    const float* b_qkv  = (const float*)d_in[2];
    const float* q_ln_w = (const float*)d_in[3];
    const float* k_ln_w = (const float*)d_in[4];
    const float* w_out  = (const float*)d_in[5];
    const float* b_out  = (const float*)d_in[6];
    float* out = (float*)d_out;

    float* qkv;  cudaGetSymbolAddress((void**)&qkv,  g_qkv);
    float* attn; cudaGetSymbolAddress((void**)&attn, g_attn);

    // 1) QKV projection: [6144,2048] @ [2048,6144] + b
    {
        dim3 grid(QKVN / 128, ROWS / 128);
        sgemm_bias_kernel<<<grid, 256>>>(x, w_qkv, b_qkv, qkv, ROWS, QKVN, DIM);
    }
    // 2) QK RMSNorm (in place)
    {
        dim3 grid(ROWS, 2);
        rmsnorm_kernel<<<grid, 256>>>(qkv, q_ln_w, k_ln_w);
    }
    // 3) Causal attention
    {
        static int smem_set = 0;
        const int smem = (3 * 128 * 64 + 64 * 64) * (int)sizeof(float); // 114688
        cudaFuncSetAttribute(attn_kernel, cudaFuncAttributeMaxDynamicSharedMemorySize, smem);
        (void)smem_set;
        dim3 grid(SEQ / 64, BATCH * NHEAD);
        attn_kernel<<<grid, 256, smem>>>(qkv, attn);
    }
    // 4) Output projection: [6144,2048] @ [2048,2048] + b -> d_out
    {
        dim3 grid(DIM / 128, ROWS / 128);
        sgemm_bias_kernel<<<grid, 256>>>(attn, w_out, b_out, out, ROWS, DIM, DIM);
    }
}

// round 4
// speedup vs baseline: 1.6236x; 1.6236x over previous
#include <cuda_runtime.h>
#include <cuda_bf16.h>
#include <math_constants.h>
#include <cstdint>

// Problem constants
#define BATCH 4
#define SEQ   1536
#define DIM   2048
#define NHEAD 16
#define HD    128
#define ROWS  (BATCH*SEQ)    // 6144
#define QKVN  (3*DIM)        // 6144

// ---------------------------------------------------------------------------
// Scratch (device globals: allocation-free rule)
// ---------------------------------------------------------------------------
__device__ float g_qkv[(size_t)ROWS * QKVN];               // [6144,6144] fp32
__device__ float g_attn[(size_t)ROWS * DIM];               // [6144,2048] fp32
__device__ __nv_bfloat16 g_a_hi[(size_t)ROWS * DIM];       // split of x / attn
__device__ __nv_bfloat16 g_a_lo[(size_t)ROWS * DIM];
__device__ __nv_bfloat16 g_wq_hi[(size_t)QKVN * DIM];      // w_qkv^T split [N=6144][K=2048]
__device__ __nv_bfloat16 g_wq_lo[(size_t)QKVN * DIM];
__device__ __nv_bfloat16 g_wo_hi[(size_t)DIM * DIM];       // w_out^T split [2048][2048]
__device__ __nv_bfloat16 g_wo_lo[(size_t)DIM * DIM];

// ---------------------------------------------------------------------------
// helpers
// ---------------------------------------------------------------------------
__device__ __forceinline__ uint32_t smem_u32(const void* p) {
    uint32_t a;
    asm("{ .reg .u64 t; cvta.to.shared.u64 t, %1; cvt.u32.u64 %0, t; }" : "=r"(a) : "l"(p));
    return a;
}
__device__ __forceinline__ void cp_async16(uint32_t dst, const void* src) {
    asm volatile("cp.async.cg.shared.global [%0], [%1], 16;" :: "r"(dst), "l"(src) : "memory");
}
#define CP_COMMIT() asm volatile("cp.async.commit_group;" ::: "memory")
#define CP_WAIT(n)  asm volatile("cp.async.wait_group %0;" :: "n"(n) : "memory")

// mma.sync m16n8k16 bf16 -> f32 (family-compatible HMMA; compiles on compute_103)
__device__ __forceinline__ void mma_bf16(float* d, const uint32_t* a, const uint32_t* b) {
    asm volatile(
        "mma.sync.aligned.m16n8k16.row.col.f32.bf16.bf16.f32 "
        "{%0,%1,%2,%3}, {%4,%5,%6,%7}, {%8,%9}, {%0,%1,%2,%3};"
        : "+f"(d[0]), "+f"(d[1]), "+f"(d[2]), "+f"(d[3])
        : "r"(a[0]), "r"(a[1]), "r"(a[2]), "r"(a[3]), "r"(b[0]), "r"(b[1]));
}

// ---------------------------------------------------------------------------
// bf16x3 HMMA GEMM: C[M,N] = (Ah+Al)[M,K] @ (Bh+Bl)[N,K]^T + bias
// 128x128 tile, KB=32, 256 threads (8 warps, 2x4), cp.async double buffer.
// ---------------------------------------------------------------------------
#define GMT 128
#define GNT 128
#define GKB 32
#define KPITCH 40                         // bf16 elements per smem row
#define STG_ELEMS (128 * KPITCH)          // per array
#define STG_ARRAYS 4                      // Ah, Al, Bh, Bl
#define GSMEM_BYTES (2 * STG_ARRAYS * STG_ELEMS * 2)   // 81920

__global__ __launch_bounds__(256) void gemm_hmma_kernel(
    const __nv_bfloat16* __restrict__ Ah, const __nv_bfloat16* __restrict__ Al,
    const __nv_bfloat16* __restrict__ Bh, const __nv_bfloat16* __restrict__ Bl,
    const float* __restrict__ bias, float* __restrict__ C,
    int N, int K)
{
    extern __shared__ __align__(16) __nv_bfloat16 sm[];
    const int tid  = threadIdx.x;
    const int wid  = tid >> 5;
    const int lane = tid & 31;
    const int row0 = blockIdx.y * GMT;
    const int col0 = blockIdx.x * GNT;
    const int warp_m = (wid >> 2) * 64;   // 0 or 64
    const int warp_n = (wid & 3) * 32;    // 0,32,64,96
    const int nkb = K / GKB;

    const uint32_t sbase = smem_u32(sm);

    float acc[4][4][4];
    #pragma unroll
    for (int i = 0; i < 4; i++)
        #pragma unroll
        for (int j = 0; j < 4; j++)
            #pragma unroll
            for (int q = 0; q < 4; q++) acc[i][j][q] = 0.0f;

    const __nv_bfloat16* gsrc[4] = {Ah, Al, Bh, Bl};

    // issue cp.async for one stage (all 4 arrays); 2 chunks/thread/array
    auto issue_stage = [&](int s, int kb) {
        const int koff = kb * GKB;
        #pragma unroll
        for (int a = 0; a < 4; a++) {
            const int gbase = (a < 2) ? row0 : col0;
            const uint32_t dstb = sbase + (uint32_t)((s * STG_ARRAYS + a) * STG_ELEMS) * 2;
            #pragma unroll
            for (int rep = 0; rep < 2; rep++) {
                const int chunk = tid + rep * 256;     // 0..511
                const int r = chunk >> 2;              // 0..127
                const int c8 = (chunk & 3) * 8;        // 0,8,16,24
                const __nv_bfloat16* g = gsrc[a] + (size_t)(gbase + r) * K + koff + c8;
                cp_async16(dstb + (uint32_t)(r * KPITCH + c8) * 2, g);
            }
        }
    };

    issue_stage(0, 0);
    CP_COMMIT();

    for (int kb = 0; kb < nkb; kb++) {
        const int p = kb & 1;
        if (kb + 1 < nkb) {
            issue_stage(p ^ 1, kb + 1);
            CP_COMMIT();
            CP_WAIT(1);
        } else {
            CP_WAIT(0);
        }
        __syncthreads();

        const __nv_bfloat16* Ahs = sm + (p * STG_ARRAYS + 0) * STG_ELEMS;
        const __nv_bfloat16* Als = sm + (p * STG_ARRAYS + 1) * STG_ELEMS;
        const __nv_bfloat16* Bhs = sm + (p * STG_ARRAYS + 2) * STG_ELEMS;
        const __nv_bfloat16* Bls = sm + (p * STG_ARRAYS + 3) * STG_ELEMS;

        #pragma unroll
        for (int ks = 0; ks < 2; ks++) {
            const int k0 = ks * 16;
            const int cfrag = k0 + (lane & 3) * 2;
            uint32_t afh[4][4], afl[4][4];
            #pragma unroll
            for (int i = 0; i < 4; i++) {
                const int r = warp_m + i * 16 + (lane >> 2);
                afh[i][0] = *(const uint32_t*)&Ahs[r * KPITCH + cfrag];
                afh[i][1] = *(const uint32_t*)&Ahs[(r + 8) * KPITCH + cfrag];
                afh[i][2] = *(const uint32_t*)&Ahs[r * KPITCH + cfrag + 8];
                afh[i][3] = *(const uint32_t*)&Ahs[(r + 8) * KPITCH + cfrag + 8];
                afl[i][0] = *(const uint32_t*)&Als[r * KPITCH + cfrag];
                afl[i][1] = *(const uint32_t*)&Als[(r + 8) * KPITCH + cfrag];
                afl[i][2] = *(const uint32_t*)&Als[r * KPITCH + cfrag + 8];
                afl[i][3] = *(const uint32_t*)&Als[(r + 8) * KPITCH + cfrag + 8];
            }
            uint32_t bfh[4][2], bfl[4][2];
            #pragma unroll
            for (int j = 0; j < 4; j++) {
                const int n = warp_n + j * 8 + (lane >> 2);
                bfh[j][0] = *(const uint32_t*)&Bhs[n * KPITCH + cfrag];
                bfh[j][1] = *(const uint32_t*)&Bhs[n * KPITCH + cfrag + 8];
                bfl[j][0] = *(const uint32_t*)&Bls[n * KPITCH + cfrag];
                bfl[j][1] = *(const uint32_t*)&Bls[n * KPITCH + cfrag + 8];
            }
            #pragma unroll
            for (int i = 0; i < 4; i++)
                #pragma unroll
                for (int j = 0; j < 4; j++) {
                    mma_bf16(acc[i][j], afh[i], bfh[j]);   // hi*hi
                    mma_bf16(acc[i][j], afh[i], bfl[j]);   // hi*lo
                    mma_bf16(acc[i][j], afl[i], bfh[j]);   // lo*hi
                }
        }
        __syncthreads();
    }

    // epilogue: + bias, float2 stores (d0d1 -> row, d2d3 -> row+8)
    #pragma unroll
    for (int i = 0; i < 4; i++) {
        #pragma unroll
        for (int j = 0; j < 4; j++) {
            const int r = row0 + warp_m + i * 16 + (lane >> 2);
            const int c = col0 + warp_n + j * 8 + (lane & 3) * 2;
            const float b0 = bias[c], b1 = bias[c + 1];
            float2 v0 = {acc[i][j][0] + b0, acc[i][j][1] + b1};
            float2 v1 = {acc[i][j][2] + b0, acc[i][j][3] + b1};
            *(float2*)&C[(size_t)r * N + c]       = v0;
            *(float2*)&C[(size_t)(r + 8) * N + c] = v1;
        }
    }
}

// ---------------------------------------------------------------------------
// fp32 -> bf16 hi/lo split (same layout)
// ---------------------------------------------------------------------------
__global__ __launch_bounds__(256) void split_bf16_kernel(
    const float* __restrict__ src, __nv_bfloat16* __restrict__ hi,
    __nv_bfloat16* __restrict__ lo, int n4)
{
    const int i = blockIdx.x * 256 + threadIdx.x;
    if (i >= n4) return;
    float4 v = ((const float4*)src)[i];
    float vv[4] = {v.x, v.y, v.z, v.w};
    __nv_bfloat16 h[4], l[4];
    #pragma unroll
    for (int k = 0; k < 4; k++) {
        h[k] = __float2bfloat16(vv[k]);
        l[k] = __float2bfloat16(vv[k] - __bfloat162float(h[k]));
    }
    *(uint2*)(hi + (size_t)i * 4) = *(uint2*)h;
    *(uint2*)(lo + (size_t)i * 4) = *(uint2*)l;
}

// ---------------------------------------------------------------------------
// W[K][N] fp32 -> Wt[N][K] bf16 hi/lo (transpose + split)
// ---------------------------------------------------------------------------
__global__ __launch_bounds__(256) void transpose_split_kernel(
    const float* __restrict__ W, __nv_bfloat16* __restrict__ Th,
    __nv_bfloat16* __restrict__ Tl, int K, int N)
{
    __shared__ float ts[32][33];
    const int k0 = blockIdx.y * 32, n0 = blockIdx.x * 32;
    const int tx = threadIdx.x & 31, ty = threadIdx.x >> 5;
    #pragma unroll
    for (int i = 0; i < 32; i += 8)
        ts[ty + i][tx] = W[(size_t)(k0 + ty + i) * N + n0 + tx];
    __syncthreads();
    #pragma unroll
    for (int i = 0; i < 32; i += 8) {
        const float v = ts[tx][ty + i];
        const __nv_bfloat16 h = __float2bfloat16(v);
        const __nv_bfloat16 l = __float2bfloat16(v - __bfloat162float(h));
        const size_t o = (size_t)(n0 + ty + i) * K + k0 + tx;
        Th[o] = h; Tl[o] = l;
    }
}

// ---------------------------------------------------------------------------
// RMSNorm over hidden dim (2048), in place on q (y=0) / k (y=1) thirds.
// ---------------------------------------------------------------------------
__global__ __launch_bounds__(256) void rmsnorm_kernel(
    float* __restrict__ qkv, const float* __restrict__ qw, const float* __restrict__ kw)
{
    const int row   = blockIdx.x;
    const int which = blockIdx.y;
    float* p = qkv + (size_t)row * QKVN + which * DIM;
    const float* w = which ? kw : qw;
    const int tid = threadIdx.x;

    float4 v0 = *(const float4*)(p + tid * 8);
    float4 v1 = *(const float4*)(p + tid * 8 + 4);
    float ss = v0.x*v0.x + v0.y*v0.y + v0.z*v0.z + v0.w*v0.w
             + v1.x*v1.x + v1.y*v1.y + v1.z*v1.z + v1.w*v1.w;
    #pragma unroll
    for (int off = 16; off > 0; off >>= 1)
        ss += __shfl_xor_sync(0xffffffffu, ss, off);

    __shared__ float warpsum[8];
    __shared__ float s_rn;
    if ((tid & 31) == 0) warpsum[tid >> 5] = ss;
    __syncthreads();
    if (tid == 0) {
        float tot = 0.f;
        #pragma unroll
        for (int i = 0; i < 8; i++) tot += warpsum[i];
        s_rn = rsqrtf(tot * (1.0f / DIM) + 1e-6f);
    }
    __syncthreads();
    const float rn = s_rn;

    const float* wp = w + tid * 8;
    float4 w0 = *(const float4*)(wp);
    float4 w1 = *(const float4*)(wp + 4);
    v0.x *= rn * w0.x; v0.y *= rn * w0.y; v0.z *= rn * w0.z; v0.w *= rn * w0.w;
    v1.x *= rn * w1.x; v1.y *= rn * w1.y; v1.z *= rn * w1.z; v1.w *= rn * w1.w;
    *(float4*)(p + tid * 8)     = v0;
    *(float4*)(p + tid * 8 + 4) = v1;
}

// ---------------------------------------------------------------------------
// Flash-style causal attention (fp32), unchanged from round 1 (known-good).
// ---------------------------------------------------------------------------
__global__ __launch_bounds__(256) void attn_kernel(
    const float* __restrict__ qkv, float* __restrict__ out)
{
    extern __shared__ float smf[];
    float* Qt = smf;
    float* Kt = smf + 128 * 64;
    float* Vs = smf + 2 * 128 * 64;
    float* Pt = smf + 3 * 128 * 64;

    const int qtile = blockIdx.x;
    const int bh    = blockIdx.y;
    const int b = bh >> 4;
    const int h = bh & 15;
    const int tid = threadIdx.x;
    const int tx = tid & 15;
    const int ty = tid >> 4;

    const size_t rowstride = QKVN;
    const float* qbase = qkv + (size_t)b * SEQ * rowstride + h * HD;
    const float* kbase = qbase + DIM;
    const float* vbase = qbase + 2 * DIM;

    {
        const int r  = tid >> 2;
        const int c0 = (tid & 3) * 32;
        const float* src = qbase + (size_t)(qtile * 64 + r) * rowstride + c0;
        #pragma unroll
        for (int c = 0; c < 32; c += 4) {
            float4 v = *(const float4*)(src + c);
            Qt[(c0 + c + 0) * 64 + r] = v.x;
            Qt[(c0 + c + 1) * 64 + r] = v.y;
            Qt[(c0 + c + 2) * 64 + r] = v.z;
            Qt[(c0 + c + 3) * 64 + r] = v.w;
        }
    }

    float o[4][8];
    #pragma unroll
    for (int i = 0; i < 4; i++)
        #pragma unroll
        for (int c = 0; c < 8; c++) o[i][c] = 0.0f;
    float m_i[4] = {-CUDART_INF_F, -CUDART_INF_F, -CUDART_INF_F, -CUDART_INF_F};
    float l_i[4] = {0.f, 0.f, 0.f, 0.f};
    const float scale = 0.08838834764831845f;

    for (int kt = 0; kt <= qtile; kt++) {
        __syncthreads();
        {
            const int r  = tid >> 2;
            const int c0 = (tid & 3) * 32;
            const size_t krow = (size_t)(kt * 64 + r);
            const float* ksrc = kbase + krow * rowstride + c0;
            const float* vsrc = vbase + krow * rowstride + c0;
            #pragma unroll
            for (int c = 0; c < 32; c += 4) {
                float4 kv = *(const float4*)(ksrc + c);
                Kt[(c0 + c + 0) * 64 + r] = kv.x;
                Kt[(c0 + c + 1) * 64 + r] = kv.y;
                Kt[(c0 + c + 2) * 64 + r] = kv.z;
                Kt[(c0 + c + 3) * 64 + r] = kv.w;
                *(float4*)&Vs[r * 128 + c0 + c] = *(const float4*)(vsrc + c);
            }
        }
        __syncthreads();

        float s[4][4];
        #pragma unroll
        for (int i = 0; i < 4; i++)
            #pragma unroll
            for (int j = 0; j < 4; j++) s[i][j] = 0.0f;

        for (int kk = 0; kk < 128; kk++) {
            float4 qv = *(const float4*)&Qt[kk * 64 + ty * 4];
            float4 kv = *(const float4*)&Kt[kk * 64 + tx * 4];
            float qr[4] = {qv.x, qv.y, qv.z, qv.w};
            float kr[4] = {kv.x, kv.y, kv.z, kv.w};
            #pragma unroll
            for (int i = 0; i < 4; i++)
                #pragma unroll
                for (int j = 0; j < 4; j++)
                    s[i][j] = fmaf(qr[i], kr[j], s[i][j]);
        }

        if (kt == qtile) {
            #pragma unroll
            for (int i = 0; i < 4; i++)
                #pragma unroll
                for (int j = 0; j < 4; j++) {
                    const int qr = ty * 4 + i, kr = tx * 4 + j;
                    s[i][j] = (kr > qr) ? -1e30f : s[i][j] * scale;
                }
        } else {
            #pragma unroll
            for (int i = 0; i < 4; i++)
                #pragma unroll
                for (int j = 0; j < 4; j++) s[i][j] *= scale;
        }

        float p[4][4];
        #pragma unroll
        for (int i = 0; i < 4; i++) {
            float rm = fmaxf(fmaxf(s[i][0], s[i][1]), fmaxf(s[i][2], s[i][3]));
            #pragma unroll
            for (int off = 1; off < 16; off <<= 1)
                rm = fmaxf(rm, __shfl_xor_sync(0xffffffffu, rm, off));
            const float mnew = fmaxf(m_i[i], rm);
            const float corr = __expf(m_i[i] - mnew);
            m_i[i] = mnew;
            float sum = 0.f;
            #pragma unroll
            for (int j = 0; j < 4; j++) {
                p[i][j] = __expf(s[i][j] - mnew);
                sum += p[i][j];
            }
            #pragma unroll
            for (int off = 1; off < 16; off <<= 1)
                sum += __shfl_xor_sync(0xffffffffu, sum, off);
            l_i[i] = l_i[i] * corr + sum;
            #pragma unroll
            for (int c = 0; c < 8; c++) o[i][c] *= corr;
        }

        #pragma unroll
        for (int j = 0; j < 4; j++)
            #pragma unroll
            for (int i = 0; i < 4; i++)
                Pt[(tx * 4 + j) * 64 + ty * 4 + i] = p[i][j];
        __syncthreads();

        for (int kk = 0; kk < 64; kk++) {
            float4 pv = *(const float4*)&Pt[kk * 64 + ty * 4];
            float4 v0 = *(const float4*)&Vs[kk * 128 + tx * 8];
            float4 v1 = *(const float4*)&Vs[kk * 128 + tx * 8 + 4];
            float pr[4] = {pv.x, pv.y, pv.z, pv.w};
            float vr[8] = {v0.x, v0.y, v0.z, v0.w, v1.x, v1.y, v1.z, v1.w};
            #pragma unroll
            for (int i = 0; i < 4; i++)
                #pragma unroll
                for (int c = 0; c < 8; c++)
                    o[i][c] = fmaf(pr[i], vr[c], o[i][c]);
        }
    }

    #pragma unroll
    for (int i = 0; i < 4; i++) {
        const float inv = 1.0f / l_i[i];
        const int q = qtile * 64 + ty * 4 + i;
        float* dst = out + ((size_t)b * SEQ + q) * DIM + h * HD + tx * 8;
        float4 o0, o1;
        o0.x = o[i][0] * inv; o0.y = o[i][1] * inv; o0.z = o[i][2] * inv; o0.w = o[i][3] * inv;
        o1.x = o[i][4] * inv; o1.y = o[i][5] * inv; o1.z = o[i][6] * inv; o1.w = o[i][7] * inv;
        *(float4*)(dst)     = o0;
        *(float4*)(dst + 4) = o1;
    }
}

// ---------------------------------------------------------------------------
extern "C" void kernel_launch(void* const* d_in, const int* in_sizes, int n_in,
                              void* d_out, int out_size)
{
    const float* x      = (const float*)d_in[0];
    const float* w_qkv  = (const float*)d_in[1];
    const float* b_qkv  = (const float*)d_in[2];
    const float* q_ln_w = (const float*)d_in[3];
    const float* k_ln_w = (const float*)d_in[4];
    const float* w_out  = (const float*)d_in[5];
    const float* b_out  = (const float*)d_in[6];
    float* out = (float*)d_out;

    float *qkv, *attn;
    __nv_bfloat16 *a_hi, *a_lo, *wq_hi, *wq_lo, *wo_hi, *wo_lo;
    cudaGetSymbolAddress((void**)&qkv,   g_qkv);
    cudaGetSymbolAddress((void**)&attn,  g_attn);
    cudaGetSymbolAddress((void**)&a_hi,  g_a_hi);
    cudaGetSymbolAddress((void**)&a_lo,  g_a_lo);
    cudaGetSymbolAddress((void**)&wq_hi, g_wq_hi);
    cudaGetSymbolAddress((void**)&wq_lo, g_wq_lo);
    cudaGetSymbolAddress((void**)&wo_hi, g_wo_hi);
    cudaGetSymbolAddress((void**)&wo_lo, g_wo_lo);

    cudaFuncSetAttribute(gemm_hmma_kernel, cudaFuncAttributeMaxDynamicSharedMemorySize, GSMEM_BYTES);
    cudaFuncSetAttribute(attn_kernel, cudaFuncAttributeMaxDynamicSharedMemorySize, 114688);

    // 0) operand prep
    {
        const int n4 = ROWS * DIM / 4;
        split_bf16_kernel<<<(n4 + 255) / 256, 256>>>(x, a_hi, a_lo, n4);
        transpose_split_kernel<<<dim3(QKVN / 32, DIM / 32), 256>>>(w_qkv, wq_hi, wq_lo, DIM, QKVN);
        transpose_split_kernel<<<dim3(DIM / 32, DIM / 32), 256>>>(w_out, wo_hi, wo_lo, DIM, DIM);
    }
    // 1) QKV projection (HMMA bf16x3): [6144,2048] @ [2048,6144] + b
    {
        dim3 grid(QKVN / GNT, ROWS / GMT);   // (48, 48)
        gemm_hmma_kernel<<<grid, 256, GSMEM_BYTES>>>(a_hi, a_lo, wq_hi, wq_lo, b_qkv, qkv, QKVN, DIM);
    }
    // 2) QK RMSNorm (in place)
    {
        dim3 grid(ROWS, 2);
        rmsnorm_kernel<<<grid, 256>>>(qkv, q_ln_w, k_ln_w);
    }
    // 3) Causal attention (fp32)
    {
        dim3 grid(SEQ / 64, BATCH * NHEAD);
        attn_kernel<<<grid, 256, 114688>>>(qkv, attn);
    }
    // 4) Output projection (HMMA bf16x3)
    {
        const int n4 = ROWS * DIM / 4;
        split_bf16_kernel<<<(n4 + 255) / 256, 256>>>(attn, a_hi, a_lo, n4);
        dim3 grid(DIM / GNT, ROWS / GMT);    // (16, 48)
        gemm_hmma_kernel<<<grid, 256, GSMEM_BYTES>>>(a_hi, a_lo, wo_hi, wo_lo, b_out, out, DIM, DIM);
    }
}

// round 10
// speedup vs baseline: 1.6248x; 1.0007x over previous
#include <cuda_runtime.h>
#include <cuda_bf16.h>
#include <math_constants.h>
#include <cstdint>

// Problem constants
#define BATCH 4
#define SEQ   1536
#define DIM   2048
#define NHEAD 16
#define HD    128
#define ROWS  (BATCH*SEQ)    // 6144
#define QKVN  (3*DIM)        // 6144

// ---------------------------------------------------------------------------
// Scratch (device globals: allocation-free rule)
// ---------------------------------------------------------------------------
__device__ float g_qkv[(size_t)ROWS * QKVN];               // [6144,6144] fp32
__device__ __nv_bfloat16 g_a_hi[(size_t)ROWS * DIM];       // x split -> attn out split
__device__ __nv_bfloat16 g_a_lo[(size_t)ROWS * DIM];
__device__ __nv_bfloat16 g_wq_hi[(size_t)QKVN * DIM];      // w_qkv^T split [N][K]
__device__ __nv_bfloat16 g_wq_lo[(size_t)QKVN * DIM];
__device__ __nv_bfloat16 g_wo_hi[(size_t)DIM * DIM];       // w_out^T split
__device__ __nv_bfloat16 g_wo_lo[(size_t)DIM * DIM];

// ---------------------------------------------------------------------------
// helpers
// ---------------------------------------------------------------------------
__device__ __forceinline__ uint32_t smem_u32(const void* p) {
    uint32_t a;
    asm("{ .reg .u64 t; cvta.to.shared.u64 t, %1; cvt.u32.u64 %0, t; }" : "=r"(a) : "l"(p));
    return a;
}
__device__ __forceinline__ void cp_async16(uint32_t dst, const void* src) {
    asm volatile("cp.async.cg.shared.global [%0], [%1], 16;" :: "r"(dst), "l"(src) : "memory");
}
#define CP_COMMIT() asm volatile("cp.async.commit_group;" ::: "memory")
#define CP_WAIT(n)  asm volatile("cp.async.wait_group %0;" :: "n"(n) : "memory")

// mma.sync m16n8k16 bf16 -> f32 (validated on hardware in round 4)
__device__ __forceinline__ void mma_bf16(float* d, const uint32_t* a, const uint32_t* b) {
    asm volatile(
        "mma.sync.aligned.m16n8k16.row.col.f32.bf16.bf16.f32 "
        "{%0,%1,%2,%3}, {%4,%5,%6,%7}, {%8,%9}, {%0,%1,%2,%3};"
        : "+f"(d[0]), "+f"(d[1]), "+f"(d[2]), "+f"(d[3])
        : "r"(a[0]), "r"(a[1]), "r"(a[2]), "r"(a[3]), "r"(b[0]), "r"(b[1]));
}

// ---------------------------------------------------------------------------
// bf16x3 HMMA GEMM: C[M,N] = (Ah+Al)[M,K] @ (Bh+Bl)[N,K]^T + bias
// 128x128 tile, KB=32, 256 threads, cp.async THREE-stage pipeline.
// ---------------------------------------------------------------------------
#define GMT 128
#define GNT 128
#define GKB 32
#define KPITCH 40
#define STG_ELEMS (128 * KPITCH)
#define STG_ARRAYS 4
#define GSTAGES 3
#define GSMEM_BYTES (GSTAGES * STG_ARRAYS * STG_ELEMS * 2)   // 122880

__global__ __launch_bounds__(256) void gemm_hmma_kernel(
    const __nv_bfloat16* __restrict__ Ah, const __nv_bfloat16* __restrict__ Al,
    const __nv_bfloat16* __restrict__ Bh, const __nv_bfloat16* __restrict__ Bl,
    const float* __restrict__ bias, float* __restrict__ C,
    int N, int K)
{
    extern __shared__ __align__(16) __nv_bfloat16 sm[];
    const int tid  = threadIdx.x;
    const int wid  = tid >> 5;
    const int lane = tid & 31;
    const int row0 = blockIdx.y * GMT;
    const int col0 = blockIdx.x * GNT;
    const int warp_m = (wid >> 2) * 64;
    const int warp_n = (wid & 3) * 32;
    const int nkb = K / GKB;
    const uint32_t sbase = smem_u32(sm);

    float acc[4][4][4];
    #pragma unroll
    for (int i = 0; i < 4; i++)
        #pragma unroll
        for (int j = 0; j < 4; j++)
            #pragma unroll
            for (int q = 0; q < 4; q++) acc[i][j][q] = 0.0f;

    const __nv_bfloat16* gsrc[4] = {Ah, Al, Bh, Bl};

    auto issue_stage = [&](int s, int kb) {
        const int koff = kb * GKB;
        #pragma unroll
        for (int a = 0; a < 4; a++) {
            const int gbase = (a < 2) ? row0 : col0;
            const uint32_t dstb = sbase + (uint32_t)((s * STG_ARRAYS + a) * STG_ELEMS) * 2;
            #pragma unroll
            for (int rep = 0; rep < 2; rep++) {
                const int chunk = tid + rep * 256;
                const int r = chunk >> 2;
                const int c8 = (chunk & 3) * 8;
                const __nv_bfloat16* g = gsrc[a] + (size_t)(gbase + r) * K + koff + c8;
                cp_async16(dstb + (uint32_t)(r * KPITCH + c8) * 2, g);
            }
        }
    };

    // prologue: fill two stages
    issue_stage(0, 0);
    CP_COMMIT();
    if (nkb > 1) { issue_stage(1, 1); CP_COMMIT(); }

    for (int kb = 0; kb < nkb; kb++) {
        const int p = kb % GSTAGES;
        // ensure group kb is complete (it is the newest only when kb==nkb-1)
        if (kb < nkb - 1) { CP_WAIT(1); } else { CP_WAIT(0); }
        __syncthreads();
        // refill the stage freed in iteration kb-1
        if (kb + 2 < nkb) {
            issue_stage((kb + 2) % GSTAGES, kb + 2);
            CP_COMMIT();
        }

        const __nv_bfloat16* Ahs = sm + (p * STG_ARRAYS + 0) * STG_ELEMS;
        const __nv_bfloat16* Als = sm + (p * STG_ARRAYS + 1) * STG_ELEMS;
        const __nv_bfloat16* Bhs = sm + (p * STG_ARRAYS + 2) * STG_ELEMS;
        const __nv_bfloat16* Bls = sm + (p * STG_ARRAYS + 3) * STG_ELEMS;

        #pragma unroll
        for (int ks = 0; ks < 2; ks++) {
            const int cfrag = ks * 16 + (lane & 3) * 2;
            uint32_t afh[4][4], afl[4][4];
            #pragma unroll
            for (int i = 0; i < 4; i++) {
                const int r = warp_m + i * 16 + (lane >> 2);
                afh[i][0] = *(const uint32_t*)&Ahs[r * KPITCH + cfrag];
                afh[i][1] = *(const uint32_t*)&Ahs[(r + 8) * KPITCH + cfrag];
                afh[i][2] = *(const uint32_t*)&Ahs[r * KPITCH + cfrag + 8];
                afh[i][3] = *(const uint32_t*)&Ahs[(r + 8) * KPITCH + cfrag + 8];
                afl[i][0] = *(const uint32_t*)&Als[r * KPITCH + cfrag];
                afl[i][1] = *(const uint32_t*)&Als[(r + 8) * KPITCH + cfrag];
                afl[i][2] = *(const uint32_t*)&Als[r * KPITCH + cfrag + 8];
                afl[i][3] = *(const uint32_t*)&Als[(r + 8) * KPITCH + cfrag + 8];
            }
            uint32_t bfh[4][2], bfl[4][2];
            #pragma unroll
            for (int j = 0; j < 4; j++) {
                const int n = warp_n + j * 8 + (lane >> 2);
                bfh[j][0] = *(const uint32_t*)&Bhs[n * KPITCH + cfrag];
                bfh[j][1] = *(const uint32_t*)&Bhs[n * KPITCH + cfrag + 8];
                bfl[j][0] = *(const uint32_t*)&Bls[n * KPITCH + cfrag];
                bfl[j][1] = *(const uint32_t*)&Bls[n * KPITCH + cfrag + 8];
            }
            #pragma unroll
            for (int i = 0; i < 4; i++)
                #pragma unroll
                for (int j = 0; j < 4; j++) {
                    mma_bf16(acc[i][j], afh[i], bfh[j]);
                    mma_bf16(acc[i][j], afh[i], bfl[j]);
                    mma_bf16(acc[i][j], afl[i], bfh[j]);
                }
        }
        // no trailing sync: next iteration's post-WAIT __syncthreads fences reuse
    }

    #pragma unroll
    for (int i = 0; i < 4; i++) {
        #pragma unroll
        for (int j = 0; j < 4; j++) {
            const int r = row0 + warp_m + i * 16 + (lane >> 2);
            const int c = col0 + warp_n + j * 8 + (lane & 3) * 2;
            const float b0 = bias[c], b1 = bias[c + 1];
            float2 v0 = {acc[i][j][0] + b0, acc[i][j][1] + b1};
            float2 v1 = {acc[i][j][2] + b0, acc[i][j][3] + b1};
            *(float2*)&C[(size_t)r * N + c]       = v0;
            *(float2*)&C[(size_t)(r + 8) * N + c] = v1;
        }
    }
}

// ---------------------------------------------------------------------------
// fp32 -> bf16 hi/lo split
// ---------------------------------------------------------------------------
__global__ __launch_bounds__(256) void split_bf16_kernel(
    const float* __restrict__ src, __nv_bfloat16* __restrict__ hi,
    __nv_bfloat16* __restrict__ lo, int n4)
{
    const int i = blockIdx.x * 256 + threadIdx.x;
    if (i >= n4) return;
    float4 v = ((const float4*)src)[i];
    float vv[4] = {v.x, v.y, v.z, v.w};
    __nv_bfloat16 h[4], l[4];
    #pragma unroll
    for (int k = 0; k < 4; k++) {
        h[k] = __float2bfloat16(vv[k]);
        l[k] = __float2bfloat16(vv[k] - __bfloat162float(h[k]));
    }
    *(uint2*)(hi + (size_t)i * 4) = *(uint2*)h;
    *(uint2*)(lo + (size_t)i * 4) = *(uint2*)l;
}

// ---------------------------------------------------------------------------
// W[K][N] fp32 -> Wt[N][K] bf16 hi/lo (transpose + split)
// ---------------------------------------------------------------------------
__global__ __launch_bounds__(256) void transpose_split_kernel(
    const float* __restrict__ W, __nv_bfloat16* __restrict__ Th,
    __nv_bfloat16* __restrict__ Tl, int K, int N)
{
    __shared__ float ts[32][33];
    const int k0 = blockIdx.y * 32, n0 = blockIdx.x * 32;
    const int tx = threadIdx.x & 31, ty = threadIdx.x >> 5;
    #pragma unroll
    for (int i = 0; i < 32; i += 8)
        ts[ty + i][tx] = W[(size_t)(k0 + ty + i) * N + n0 + tx];
    __syncthreads();
    #pragma unroll
    for (int i = 0; i < 32; i += 8) {
        const float v = ts[tx][ty + i];
        const __nv_bfloat16 h = __float2bfloat16(v);
        const __nv_bfloat16 l = __float2bfloat16(v - __bfloat162float(h));
        const size_t o = (size_t)(n0 + ty + i) * K + k0 + tx;
        Th[o] = h; Tl[o] = l;
    }
}

// ---------------------------------------------------------------------------
// RMSNorm over hidden dim (2048), in place on q (y=0) / k (y=1) thirds.
// ---------------------------------------------------------------------------
__global__ __launch_bounds__(256) void rmsnorm_kernel(
    float* __restrict__ qkv, const float* __restrict__ qw, const float* __restrict__ kw)
{
    const int row   = blockIdx.x;
    const int which = blockIdx.y;
    float* p = qkv + (size_t)row * QKVN + which * DIM;
    const float* w = which ? kw : qw;
    const int tid = threadIdx.x;

    float4 v0 = *(const float4*)(p + tid * 8);
    float4 v1 = *(const float4*)(p + tid * 8 + 4);
    float ss = v0.x*v0.x + v0.y*v0.y + v0.z*v0.z + v0.w*v0.w
             + v1.x*v1.x + v1.y*v1.y + v1.z*v1.z + v1.w*v1.w;
    #pragma unroll
    for (int off = 16; off > 0; off >>= 1)
        ss += __shfl_xor_sync(0xffffffffu, ss, off);

    __shared__ float warpsum[8];
    __shared__ float s_rn;
    if ((tid & 31) == 0) warpsum[tid >> 5] = ss;
    __syncthreads();
    if (tid == 0) {
        float tot = 0.f;
        #pragma unroll
        for (int i = 0; i < 8; i++) tot += warpsum[i];
        s_rn = rsqrtf(tot * (1.0f / DIM) + 1e-6f);
    }
    __syncthreads();
    const float rn = s_rn;

    const float* wp = w + tid * 8;
    float4 w0 = *(const float4*)(wp);
    float4 w1 = *(const float4*)(wp + 4);
    v0.x *= rn * w0.x; v0.y *= rn * w0.y; v0.z *= rn * w0.z; v0.w *= rn * w0.w;
    v1.x *= rn * w1.x; v1.y *= rn * w1.y; v1.z *= rn * w1.z; v1.w *= rn * w1.w;
    *(float4*)(p + tid * 8)     = v0;
    *(float4*)(p + tid * 8 + 4) = v1;
}

// ---------------------------------------------------------------------------
// Flash-style causal attention (fp32, validated). Epilogue now emits
// bf16 hi/lo split directly (removes the separate split kernel).
// ---------------------------------------------------------------------------
__global__ __launch_bounds__(256) void attn_kernel(
    const float* __restrict__ qkv,
    __nv_bfloat16* __restrict__ oh, __nv_bfloat16* __restrict__ ol)
{
    extern __shared__ float smf[];
    float* Qt = smf;
    float* Kt = smf + 128 * 64;
    float* Vs = smf + 2 * 128 * 64;
    float* Pt = smf + 3 * 128 * 64;

    const int qtile = blockIdx.x;
    const int bh    = blockIdx.y;
    const int b = bh >> 4;
    const int h = bh & 15;
    const int tid = threadIdx.x;
    const int tx = tid & 15;
    const int ty = tid >> 4;

    const size_t rowstride = QKVN;
    const float* qbase = qkv + (size_t)b * SEQ * rowstride + h * HD;
    const float* kbase = qbase + DIM;
    const float* vbase = qbase + 2 * DIM;

    {
        const int r  = tid >> 2;
        const int c0 = (tid & 3) * 32;
        const float* src = qbase + (size_t)(qtile * 64 + r) * rowstride + c0;
        #pragma unroll
        for (int c = 0; c < 32; c += 4) {
            float4 v = *(const float4*)(src + c);
            Qt[(c0 + c + 0) * 64 + r] = v.x;
            Qt[(c0 + c + 1) * 64 + r] = v.y;
            Qt[(c0 + c + 2) * 64 + r] = v.z;
            Qt[(c0 + c + 3) * 64 + r] = v.w;
        }
    }

    float o[4][8];
    #pragma unroll
    for (int i = 0; i < 4; i++)
        #pragma unroll
        for (int c = 0; c < 8; c++) o[i][c] = 0.0f;
    float m_i[4] = {-CUDART_INF_F, -CUDART_INF_F, -CUDART_INF_F, -CUDART_INF_F};
    float l_i[4] = {0.f, 0.f, 0.f, 0.f};
    const float scale = 0.08838834764831845f;

    for (int kt = 0; kt <= qtile; kt++) {
        __syncthreads();
        {
            const int r  = tid >> 2;
            const int c0 = (tid & 3) * 32;
            const size_t krow = (size_t)(kt * 64 + r);
            const float* ksrc = kbase + krow * rowstride + c0;
            const float* vsrc = vbase + krow * rowstride + c0;
            #pragma unroll
            for (int c = 0; c < 32; c += 4) {
                float4 kv = *(const float4*)(ksrc + c);
                Kt[(c0 + c + 0) * 64 + r] = kv.x;
                Kt[(c0 + c + 1) * 64 + r] = kv.y;
                Kt[(c0 + c + 2) * 64 + r] = kv.z;
                Kt[(c0 + c + 3) * 64 + r] = kv.w;
                *(float4*)&Vs[r * 128 + c0 + c] = *(const float4*)(vsrc + c);
            }
        }
        __syncthreads();

        float s[4][4];
        #pragma unroll
        for (int i = 0; i < 4; i++)
            #pragma unroll
            for (int j = 0; j < 4; j++) s[i][j] = 0.0f;

        for (int kk = 0; kk < 128; kk++) {
            float4 qv = *(const float4*)&Qt[kk * 64 + ty * 4];
            float4 kv = *(const float4*)&Kt[kk * 64 + tx * 4];
            float qr[4] = {qv.x, qv.y, qv.z, qv.w};
            float kr[4] = {kv.x, kv.y, kv.z, kv.w};
            #pragma unroll
            for (int i = 0; i < 4; i++)
                #pragma unroll
                for (int j = 0; j < 4; j++)
                    s[i][j] = fmaf(qr[i], kr[j], s[i][j]);
        }

        if (kt == qtile) {
            #pragma unroll
            for (int i = 0; i < 4; i++)
                #pragma unroll
                for (int j = 0; j < 4; j++) {
                    const int qr = ty * 4 + i, kr = tx * 4 + j;
                    s[i][j] = (kr > qr) ? -1e30f : s[i][j] * scale;
                }
        } else {
            #pragma unroll
            for (int i = 0; i < 4; i++)
                #pragma unroll
                for (int j = 0; j < 4; j++) s[i][j] *= scale;
        }

        float p[4][4];
        #pragma unroll
        for (int i = 0; i < 4; i++) {
            float rm = fmaxf(fmaxf(s[i][0], s[i][1]), fmaxf(s[i][2], s[i][3]));
            #pragma unroll
            for (int off = 1; off < 16; off <<= 1)
                rm = fmaxf(rm, __shfl_xor_sync(0xffffffffu, rm, off));
            const float mnew = fmaxf(m_i[i], rm);
            const float corr = __expf(m_i[i] - mnew);
            m_i[i] = mnew;
            float sum = 0.f;
            #pragma unroll
            for (int j = 0; j < 4; j++) {
                p[i][j] = __expf(s[i][j] - mnew);
                sum += p[i][j];
            }
            #pragma unroll
            for (int off = 1; off < 16; off <<= 1)
                sum += __shfl_xor_sync(0xffffffffu, sum, off);
            l_i[i] = l_i[i] * corr + sum;
            #pragma unroll
            for (int c = 0; c < 8; c++) o[i][c] *= corr;
        }

        #pragma unroll
        for (int j = 0; j < 4; j++)
            #pragma unroll
            for (int i = 0; i < 4; i++)
                Pt[(tx * 4 + j) * 64 + ty * 4 + i] = p[i][j];
        __syncthreads();

        for (int kk = 0; kk < 64; kk++) {
            float4 pv = *(const float4*)&Pt[kk * 64 + ty * 4];
            float4 v0 = *(const float4*)&Vs[kk * 128 + tx * 8];
            float4 v1 = *(const float4*)&Vs[kk * 128 + tx * 8 + 4];
            float pr[4] = {pv.x, pv.y, pv.z, pv.w};
            float vr[8] = {v0.x, v0.y, v0.z, v0.w, v1.x, v1.y, v1.z, v1.w};
            #pragma unroll
            for (int i = 0; i < 4; i++)
                #pragma unroll
                for (int c = 0; c < 8; c++)
                    o[i][c] = fmaf(pr[i], vr[c], o[i][c]);
        }
    }

    // epilogue: normalize, split to bf16 hi/lo, store (feeds GEMM2 directly)
    #pragma unroll
    for (int i = 0; i < 4; i++) {
        const float inv = 1.0f / l_i[i];
        const int q = qtile * 64 + ty * 4 + i;
        const size_t off = ((size_t)b * SEQ + q) * DIM + h * HD + tx * 8;
        __nv_bfloat16 hh[8], ll[8];
        #pragma unroll
        for (int c = 0; c < 8; c++) {
            const float v = o[i][c] * inv;
            hh[c] = __float2bfloat16(v);
            ll[c] = __float2bfloat16(v - __bfloat162float(hh[c]));
        }
        *(uint4*)(oh + off) = *(uint4*)hh;
        *(uint4*)(ol + off) = *(uint4*)ll;
    }
}

// ---------------------------------------------------------------------------
extern "C" void kernel_launch(void* const* d_in, const int* in_sizes, int n_in,
                              void* d_out, int out_size)
{
    const float* x      = (const float*)d_in[0];
    const float* w_qkv  = (const float*)d_in[1];
    const float* b_qkv  = (const float*)d_in[2];
    const float* q_ln_w = (const float*)d_in[3];
    const float* k_ln_w = (const float*)d_in[4];
    const float* w_out  = (const float*)d_in[5];
    const float* b_out  = (const float*)d_in[6];
    float* out = (float*)d_out;

    float* qkv;
    __nv_bfloat16 *a_hi, *a_lo, *wq_hi, *wq_lo, *wo_hi, *wo_lo;
    cudaGetSymbolAddress((void**)&qkv,   g_qkv);
    cudaGetSymbolAddress((void**)&a_hi,  g_a_hi);
    cudaGetSymbolAddress((void**)&a_lo,  g_a_lo);
    cudaGetSymbolAddress((void**)&wq_hi, g_wq_hi);
    cudaGetSymbolAddress((void**)&wq_lo, g_wq_lo);
    cudaGetSymbolAddress((void**)&wo_hi, g_wo_hi);
    cudaGetSymbolAddress((void**)&wo_lo, g_wo_lo);

    cudaFuncSetAttribute(gemm_hmma_kernel, cudaFuncAttributeMaxDynamicSharedMemorySize, GSMEM_BYTES);
    cudaFuncSetAttribute(attn_kernel, cudaFuncAttributeMaxDynamicSharedMemorySize, 114688);

    // 0) operand prep
    {
        const int n4 = ROWS * DIM / 4;
        split_bf16_kernel<<<(n4 + 255) / 256, 256>>>(x, a_hi, a_lo, n4);
        transpose_split_kernel<<<dim3(QKVN / 32, DIM / 32), 256>>>(w_qkv, wq_hi, wq_lo, DIM, QKVN);
        transpose_split_kernel<<<dim3(DIM / 32, DIM / 32), 256>>>(w_out, wo_hi, wo_lo, DIM, DIM);
    }
    // 1) QKV projection (HMMA bf16x3, 3-stage pipeline)
    {
        dim3 grid(QKVN / GNT, ROWS / GMT);   // (48, 48)
        gemm_hmma_kernel<<<grid, 256, GSMEM_BYTES>>>(a_hi, a_lo, wq_hi, wq_lo, b_qkv, qkv, QKVN, DIM);
    }
    // 2) QK RMSNorm (in place, fp32)
    {
        dim3 grid(ROWS, 2);
        rmsnorm_kernel<<<grid, 256>>>(qkv, q_ln_w, k_ln_w);
    }
    // 3) Causal attention (fp32, validated) -> bf16 hi/lo split output
    {
        dim3 grid(SEQ / 64, BATCH * NHEAD);
        attn_kernel<<<grid, 256, 114688>>>(qkv, a_hi, a_lo);
    }
    // 4) Output projection (HMMA bf16x3, 3-stage pipeline)
    {
        dim3 grid(DIM / GNT, ROWS / GMT);    // (16, 48)
        gemm_hmma_kernel<<<grid, 256, GSMEM_BYTES>>>(a_hi, a_lo, wo_hi, wo_lo, b_out, out, DIM, DIM);
    }
}

// round 11
// speedup vs baseline: 1.7286x; 1.0639x over previous
#include <cuda_runtime.h>
#include <cuda_bf16.h>
#include <math_constants.h>
#include <cstdint>

// Problem constants
#define BATCH 4
#define SEQ   1536
#define DIM   2048
#define NHEAD 16
#define HD    128
#define ROWS  (BATCH*SEQ)    // 6144
#define QKVN  (3*DIM)        // 6144

// ---------------------------------------------------------------------------
// Scratch (device globals: allocation-free rule)
// ---------------------------------------------------------------------------
__device__ float g_qkv[(size_t)ROWS * QKVN];               // [6144,6144] fp32
__device__ __nv_bfloat16 g_a_hi[(size_t)ROWS * DIM];       // x split -> attn out split
__device__ __nv_bfloat16 g_a_lo[(size_t)ROWS * DIM];
__device__ __nv_bfloat16 g_wq_hi[(size_t)QKVN * DIM];      // w_qkv^T split [N][K]
__device__ __nv_bfloat16 g_wq_lo[(size_t)QKVN * DIM];
__device__ __nv_bfloat16 g_wo_hi[(size_t)DIM * DIM];       // w_out^T split
__device__ __nv_bfloat16 g_wo_lo[(size_t)DIM * DIM];

// ---------------------------------------------------------------------------
// helpers
// ---------------------------------------------------------------------------
__device__ __forceinline__ uint32_t smem_u32(const void* p) {
    uint32_t a;
    asm("{ .reg .u64 t; cvta.to.shared.u64 t, %1; cvt.u32.u64 %0, t; }" : "=r"(a) : "l"(p));
    return a;
}
__device__ __forceinline__ void cp_async16(uint32_t dst, const void* src) {
    asm volatile("cp.async.cg.shared.global [%0], [%1], 16;" :: "r"(dst), "l"(src) : "memory");
}
#define CP_COMMIT() asm volatile("cp.async.commit_group;" ::: "memory")
#define CP_WAIT(n)  asm volatile("cp.async.wait_group %0;" :: "n"(n) : "memory")

// mma.sync m16n8k16 bf16 -> f32 (validated on hardware in round 4)
__device__ __forceinline__ void mma_bf16(float* d, const uint32_t* a, const uint32_t* b) {
    asm volatile(
        "mma.sync.aligned.m16n8k16.row.col.f32.bf16.bf16.f32 "
        "{%0,%1,%2,%3}, {%4,%5,%6,%7}, {%8,%9}, {%0,%1,%2,%3};"
        : "+f"(d[0]), "+f"(d[1]), "+f"(d[2]), "+f"(d[3])
        : "r"(a[0]), "r"(a[1]), "r"(a[2]), "r"(a[3]), "r"(b[0]), "r"(b[1]));
}

// ---------------------------------------------------------------------------
// bf16x3 HMMA GEMM: C[M,N] = (Ah+Al)[M,K] @ (Bh+Bl)[N,K]^T + bias
// 128x128 tile, KB=32, 256 threads, cp.async double buffer.
// __launch_bounds__(256,2): cap regs at 128 so TWO CTAs co-reside per SM.
// ---------------------------------------------------------------------------
#define GMT 128
#define GNT 128
#define GKB 32
#define KPITCH 40
#define STG_ELEMS (128 * KPITCH)
#define STG_ARRAYS 4
#define GSMEM_BYTES (2 * STG_ARRAYS * STG_ELEMS * 2)   // 81920 (x2 CTAs = 160KB/SM)

__global__ __launch_bounds__(256, 2) void gemm_hmma_kernel(
    const __nv_bfloat16* __restrict__ Ah, const __nv_bfloat16* __restrict__ Al,
    const __nv_bfloat16* __restrict__ Bh, const __nv_bfloat16* __restrict__ Bl,
    const float* __restrict__ bias, float* __restrict__ C,
    int N, int K)
{
    extern __shared__ __align__(16) __nv_bfloat16 sm[];
    const int tid  = threadIdx.x;
    const int wid  = tid >> 5;
    const int lane = tid & 31;
    const int row0 = blockIdx.y * GMT;
    const int col0 = blockIdx.x * GNT;
    const int warp_m = (wid >> 2) * 64;
    const int warp_n = (wid & 3) * 32;
    const int nkb = K / GKB;
    const uint32_t sbase = smem_u32(sm);

    float acc[4][4][4];
    #pragma unroll
    for (int i = 0; i < 4; i++)
        #pragma unroll
        for (int j = 0; j < 4; j++)
            #pragma unroll
            for (int q = 0; q < 4; q++) acc[i][j][q] = 0.0f;

    const __nv_bfloat16* gsrc[4] = {Ah, Al, Bh, Bl};

    auto issue_stage = [&](int s, int kb) {
        const int koff = kb * GKB;
        #pragma unroll
        for (int a = 0; a < 4; a++) {
            const int gbase = (a < 2) ? row0 : col0;
            const uint32_t dstb = sbase + (uint32_t)((s * STG_ARRAYS + a) * STG_ELEMS) * 2;
            #pragma unroll
            for (int rep = 0; rep < 2; rep++) {
                const int chunk = tid + rep * 256;
                const int r = chunk >> 2;
                const int c8 = (chunk & 3) * 8;
                const __nv_bfloat16* g = gsrc[a] + (size_t)(gbase + r) * K + koff + c8;
                cp_async16(dstb + (uint32_t)(r * KPITCH + c8) * 2, g);
            }
        }
    };

    issue_stage(0, 0);
    CP_COMMIT();

    for (int kb = 0; kb < nkb; kb++) {
        const int p = kb & 1;
        if (kb + 1 < nkb) {
            issue_stage(p ^ 1, kb + 1);
            CP_COMMIT();
            CP_WAIT(1);
        } else {
            CP_WAIT(0);
        }
        __syncthreads();

        const __nv_bfloat16* Ahs = sm + (p * STG_ARRAYS + 0) * STG_ELEMS;
        const __nv_bfloat16* Als = sm + (p * STG_ARRAYS + 1) * STG_ELEMS;
        const __nv_bfloat16* Bhs = sm + (p * STG_ARRAYS + 2) * STG_ELEMS;
        const __nv_bfloat16* Bls = sm + (p * STG_ARRAYS + 3) * STG_ELEMS;

        #pragma unroll
        for (int ks = 0; ks < 2; ks++) {
            const int cfrag = ks * 16 + (lane & 3) * 2;
            uint32_t afh[4][4], afl[4][4];
            #pragma unroll
            for (int i = 0; i < 4; i++) {
                const int r = warp_m + i * 16 + (lane >> 2);
                afh[i][0] = *(const uint32_t*)&Ahs[r * KPITCH + cfrag];
                afh[i][1] = *(const uint32_t*)&Ahs[(r + 8) * KPITCH + cfrag];
                afh[i][2] = *(const uint32_t*)&Ahs[r * KPITCH + cfrag + 8];
                afh[i][3] = *(const uint32_t*)&Ahs[(r + 8) * KPITCH + cfrag + 8];
                afl[i][0] = *(const uint32_t*)&Als[r * KPITCH + cfrag];
                afl[i][1] = *(const uint32_t*)&Als[(r + 8) * KPITCH + cfrag];
                afl[i][2] = *(const uint32_t*)&Als[r * KPITCH + cfrag + 8];
                afl[i][3] = *(const uint32_t*)&Als[(r + 8) * KPITCH + cfrag + 8];
            }
            uint32_t bfh[4][2], bfl[4][2];
            #pragma unroll
            for (int j = 0; j < 4; j++) {
                const int n = warp_n + j * 8 + (lane >> 2);
                bfh[j][0] = *(const uint32_t*)&Bhs[n * KPITCH + cfrag];
                bfh[j][1] = *(const uint32_t*)&Bhs[n * KPITCH + cfrag + 8];
                bfl[j][0] = *(const uint32_t*)&Bls[n * KPITCH + cfrag];
                bfl[j][1] = *(const uint32_t*)&Bls[n * KPITCH + cfrag + 8];
            }
            #pragma unroll
            for (int i = 0; i < 4; i++)
                #pragma unroll
                for (int j = 0; j < 4; j++) {
                    mma_bf16(acc[i][j], afh[i], bfh[j]);
                    mma_bf16(acc[i][j], afh[i], bfl[j]);
                    mma_bf16(acc[i][j], afl[i], bfh[j]);
                }
        }
        __syncthreads();
    }

    #pragma unroll
    for (int i = 0; i < 4; i++) {
        #pragma unroll
        for (int j = 0; j < 4; j++) {
            const int r = row0 + warp_m + i * 16 + (lane >> 2);
            const int c = col0 + warp_n + j * 8 + (lane & 3) * 2;
            const float b0 = bias[c], b1 = bias[c + 1];
            float2 v0 = {acc[i][j][0] + b0, acc[i][j][1] + b1};
            float2 v1 = {acc[i][j][2] + b0, acc[i][j][3] + b1};
            *(float2*)&C[(size_t)r * N + c]       = v0;
            *(float2*)&C[(size_t)(r + 8) * N + c] = v1;
        }
    }
}

// ---------------------------------------------------------------------------
// fp32 -> bf16 hi/lo split
// ---------------------------------------------------------------------------
__global__ __launch_bounds__(256) void split_bf16_kernel(
    const float* __restrict__ src, __nv_bfloat16* __restrict__ hi,
    __nv_bfloat16* __restrict__ lo, int n4)
{
    const int i = blockIdx.x * 256 + threadIdx.x;
    if (i >= n4) return;
    float4 v = ((const float4*)src)[i];
    float vv[4] = {v.x, v.y, v.z, v.w};
    __nv_bfloat16 h[4], l[4];
    #pragma unroll
    for (int k = 0; k < 4; k++) {
        h[k] = __float2bfloat16(vv[k]);
        l[k] = __float2bfloat16(vv[k] - __bfloat162float(h[k]));
    }
    *(uint2*)(hi + (size_t)i * 4) = *(uint2*)h;
    *(uint2*)(lo + (size_t)i * 4) = *(uint2*)l;
}

// ---------------------------------------------------------------------------
// W[K][N] fp32 -> Wt[N][K] bf16 hi/lo (transpose + split)
// ---------------------------------------------------------------------------
__global__ __launch_bounds__(256) void transpose_split_kernel(
    const float* __restrict__ W, __nv_bfloat16* __restrict__ Th,
    __nv_bfloat16* __restrict__ Tl, int K, int N)
{
    __shared__ float ts[32][33];
    const int k0 = blockIdx.y * 32, n0 = blockIdx.x * 32;
    const int tx = threadIdx.x & 31, ty = threadIdx.x >> 5;
    #pragma unroll
    for (int i = 0; i < 32; i += 8)
        ts[ty + i][tx] = W[(size_t)(k0 + ty + i) * N + n0 + tx];
    __syncthreads();
    #pragma unroll
    for (int i = 0; i < 32; i += 8) {
        const float v = ts[tx][ty + i];
        const __nv_bfloat16 h = __float2bfloat16(v);
        const __nv_bfloat16 l = __float2bfloat16(v - __bfloat162float(h));
        const size_t o = (size_t)(n0 + ty + i) * K + k0 + tx;
        Th[o] = h; Tl[o] = l;
    }
}

// ---------------------------------------------------------------------------
// RMSNorm over hidden dim (2048), in place on q (y=0) / k (y=1) thirds.
// ---------------------------------------------------------------------------
__global__ __launch_bounds__(256) void rmsnorm_kernel(
    float* __restrict__ qkv, const float* __restrict__ qw, const float* __restrict__ kw)
{
    const int row   = blockIdx.x;
    const int which = blockIdx.y;
    float* p = qkv + (size_t)row * QKVN + which * DIM;
    const float* w = which ? kw : qw;
    const int tid = threadIdx.x;

    float4 v0 = *(const float4*)(p + tid * 8);
    float4 v1 = *(const float4*)(p + tid * 8 + 4);
    float ss = v0.x*v0.x + v0.y*v0.y + v0.z*v0.z + v0.w*v0.w
             + v1.x*v1.x + v1.y*v1.y + v1.z*v1.z + v1.w*v1.w;
    #pragma unroll
    for (int off = 16; off > 0; off >>= 1)
        ss += __shfl_xor_sync(0xffffffffu, ss, off);

    __shared__ float warpsum[8];
    __shared__ float s_rn;
    if ((tid & 31) == 0) warpsum[tid >> 5] = ss;
    __syncthreads();
    if (tid == 0) {
        float tot = 0.f;
        #pragma unroll
        for (int i = 0; i < 8; i++) tot += warpsum[i];
        s_rn = rsqrtf(tot * (1.0f / DIM) + 1e-6f);
    }
    __syncthreads();
    const float rn = s_rn;

    const float* wp = w + tid * 8;
    float4 w0 = *(const float4*)(wp);
    float4 w1 = *(const float4*)(wp + 4);
    v0.x *= rn * w0.x; v0.y *= rn * w0.y; v0.z *= rn * w0.z; v0.w *= rn * w0.w;
    v1.x *= rn * w1.x; v1.y *= rn * w1.y; v1.z *= rn * w1.z; v1.w *= rn * w1.w;
    *(float4*)(p + tid * 8)     = v0;
    *(float4*)(p + tid * 8 + 4) = v1;
}

// ---------------------------------------------------------------------------
// Flash-style causal attention (fp32, validated). Epilogue emits
// bf16 hi/lo split directly (feeds GEMM2).
// ---------------------------------------------------------------------------
__global__ __launch_bounds__(256) void attn_kernel(
    const float* __restrict__ qkv,
    __nv_bfloat16* __restrict__ oh, __nv_bfloat16* __restrict__ ol)
{
    extern __shared__ float smf[];
    float* Qt = smf;
    float* Kt = smf + 128 * 64;
    float* Vs = smf + 2 * 128 * 64;
    float* Pt = smf + 3 * 128 * 64;

    const int qtile = blockIdx.x;
    const int bh    = blockIdx.y;
    const int b = bh >> 4;
    const int h = bh & 15;
    const int tid = threadIdx.x;
    const int tx = tid & 15;
    const int ty = tid >> 4;

    const size_t rowstride = QKVN;
    const float* qbase = qkv + (size_t)b * SEQ * rowstride + h * HD;
    const float* kbase = qbase + DIM;
    const float* vbase = qbase + 2 * DIM;

    {
        const int r  = tid >> 2;
        const int c0 = (tid & 3) * 32;
        const float* src = qbase + (size_t)(qtile * 64 + r) * rowstride + c0;
        #pragma unroll
        for (int c = 0; c < 32; c += 4) {
            float4 v = *(const float4*)(src + c);
            Qt[(c0 + c + 0) * 64 + r] = v.x;
            Qt[(c0 + c + 1) * 64 + r] = v.y;
            Qt[(c0 + c + 2) * 64 + r] = v.z;
            Qt[(c0 + c + 3) * 64 + r] = v.w;
        }
    }

    float o[4][8];
    #pragma unroll
    for (int i = 0; i < 4; i++)
        #pragma unroll
        for (int c = 0; c < 8; c++) o[i][c] = 0.0f;
    float m_i[4] = {-CUDART_INF_F, -CUDART_INF_F, -CUDART_INF_F, -CUDART_INF_F};
    float l_i[4] = {0.f, 0.f, 0.f, 0.f};
    const float scale = 0.08838834764831845f;

    for (int kt = 0; kt <= qtile; kt++) {
        __syncthreads();
        {
            const int r  = tid >> 2;
            const int c0 = (tid & 3) * 32;
            const size_t krow = (size_t)(kt * 64 + r);
            const float* ksrc = kbase + krow * rowstride + c0;
            const float* vsrc = vbase + krow * rowstride + c0;
            #pragma unroll
            for (int c = 0; c < 32; c += 4) {
                float4 kv = *(const float4*)(ksrc + c);
                Kt[(c0 + c + 0) * 64 + r] = kv.x;
                Kt[(c0 + c + 1) * 64 + r] = kv.y;
                Kt[(c0 + c + 2) * 64 + r] = kv.z;
                Kt[(c0 + c + 3) * 64 + r] = kv.w;
                *(float4*)&Vs[r * 128 + c0 + c] = *(const float4*)(vsrc + c);
            }
        }
        __syncthreads();

        float s[4][4];
        #pragma unroll
        for (int i = 0; i < 4; i++)
            #pragma unroll
            for (int j = 0; j < 4; j++) s[i][j] = 0.0f;

        for (int kk = 0; kk < 128; kk++) {
            float4 qv = *(const float4*)&Qt[kk * 64 + ty * 4];
            float4 kv = *(const float4*)&Kt[kk * 64 + tx * 4];
            float qr[4] = {qv.x, qv.y, qv.z, qv.w};
            float kr[4] = {kv.x, kv.y, kv.z, kv.w};
            #pragma unroll
            for (int i = 0; i < 4; i++)
                #pragma unroll
                for (int j = 0; j < 4; j++)
                    s[i][j] = fmaf(qr[i], kr[j], s[i][j]);
        }

        if (kt == qtile) {
            #pragma unroll
            for (int i = 0; i < 4; i++)
                #pragma unroll
                for (int j = 0; j < 4; j++) {
                    const int qr = ty * 4 + i, kr = tx * 4 + j;
                    s[i][j] = (kr > qr) ? -1e30f : s[i][j] * scale;
                }
        } else {
            #pragma unroll
            for (int i = 0; i < 4; i++)
                #pragma unroll
                for (int j = 0; j < 4; j++) s[i][j] *= scale;
        }

        float p[4][4];
        #pragma unroll
        for (int i = 0; i < 4; i++) {
            float rm = fmaxf(fmaxf(s[i][0], s[i][1]), fmaxf(s[i][2], s[i][3]));
            #pragma unroll
            for (int off = 1; off < 16; off <<= 1)
                rm = fmaxf(rm, __shfl_xor_sync(0xffffffffu, rm, off));
            const float mnew = fmaxf(m_i[i], rm);
            const float corr = __expf(m_i[i] - mnew);
            m_i[i] = mnew;
            float sum = 0.f;
            #pragma unroll
            for (int j = 0; j < 4; j++) {
                p[i][j] = __expf(s[i][j] - mnew);
                sum += p[i][j];
            }
            #pragma unroll
            for (int off = 1; off < 16; off <<= 1)
                sum += __shfl_xor_sync(0xffffffffu, sum, off);
            l_i[i] = l_i[i] * corr + sum;
            #pragma unroll
            for (int c = 0; c < 8; c++) o[i][c] *= corr;
        }

        #pragma unroll
        for (int j = 0; j < 4; j++)
            #pragma unroll
            for (int i = 0; i < 4; i++)
                Pt[(tx * 4 + j) * 64 + ty * 4 + i] = p[i][j];
        __syncthreads();

        for (int kk = 0; kk < 64; kk++) {
            float4 pv = *(const float4*)&Pt[kk * 64 + ty * 4];
            float4 v0 = *(const float4*)&Vs[kk * 128 + tx * 8];
            float4 v1 = *(const float4*)&Vs[kk * 128 + tx * 8 + 4];
            float pr[4] = {pv.x, pv.y, pv.z, pv.w};
            float vr[8] = {v0.x, v0.y, v0.z, v0.w, v1.x, v1.y, v1.z, v1.w};
            #pragma unroll
            for (int i = 0; i < 4; i++)
                #pragma unroll
                for (int c = 0; c < 8; c++)
                    o[i][c] = fmaf(pr[i], vr[c], o[i][c]);
        }
    }

    // epilogue: normalize, split to bf16 hi/lo, store (feeds GEMM2 directly)
    #pragma unroll
    for (int i = 0; i < 4; i++) {
        const float inv = 1.0f / l_i[i];
        const int q = qtile * 64 + ty * 4 + i;
        const size_t off = ((size_t)b * SEQ + q) * DIM + h * HD + tx * 8;
        __nv_bfloat16 hh[8], ll[8];
        #pragma unroll
        for (int c = 0; c < 8; c++) {
            const float v = o[i][c] * inv;
            hh[c] = __float2bfloat16(v);
            ll[c] = __float2bfloat16(v - __bfloat162float(hh[c]));
        }
        *(uint4*)(oh + off) = *(uint4*)hh;
        *(uint4*)(ol + off) = *(uint4*)ll;
    }
}

// ---------------------------------------------------------------------------
extern "C" void kernel_launch(void* const* d_in, const int* in_sizes, int n_in,
                              void* d_out, int out_size)
{
    const float* x      = (const float*)d_in[0];
    const float* w_qkv  = (const float*)d_in[1];
    const float* b_qkv  = (const float*)d_in[2];
    const float* q_ln_w = (const float*)d_in[3];
    const float* k_ln_w = (const float*)d_in[4];
    const float* w_out  = (const float*)d_in[5];
    const float* b_out  = (const float*)d_in[6];
    float* out = (float*)d_out;

    float* qkv;
    __nv_bfloat16 *a_hi, *a_lo, *wq_hi, *wq_lo, *wo_hi, *wo_lo;
    cudaGetSymbolAddress((void**)&qkv,   g_qkv);
    cudaGetSymbolAddress((void**)&a_hi,  g_a_hi);
    cudaGetSymbolAddress((void**)&a_lo,  g_a_lo);
    cudaGetSymbolAddress((void**)&wq_hi, g_wq_hi);
    cudaGetSymbolAddress((void**)&wq_lo, g_wq_lo);
    cudaGetSymbolAddress((void**)&wo_hi, g_wo_hi);
    cudaGetSymbolAddress((void**)&wo_lo, g_wo_lo);

    cudaFuncSetAttribute(gemm_hmma_kernel, cudaFuncAttributeMaxDynamicSharedMemorySize, GSMEM_BYTES);
    cudaFuncSetAttribute(attn_kernel, cudaFuncAttributeMaxDynamicSharedMemorySize, 114688);

    // 0) operand prep
    {
        const int n4 = ROWS * DIM / 4;
        split_bf16_kernel<<<(n4 + 255) / 256, 256>>>(x, a_hi, a_lo, n4);
        transpose_split_kernel<<<dim3(QKVN / 32, DIM / 32), 256>>>(w_qkv, wq_hi, wq_lo, DIM, QKVN);
        transpose_split_kernel<<<dim3(DIM / 32, DIM / 32), 256>>>(w_out, wo_hi, wo_lo, DIM, DIM);
    }
    // 1) QKV projection (HMMA bf16x3, 2 CTAs/SM)
    {
        dim3 grid(QKVN / GNT, ROWS / GMT);   // (48, 48)
        gemm_hmma_kernel<<<grid, 256, GSMEM_BYTES>>>(a_hi, a_lo, wq_hi, wq_lo, b_qkv, qkv, QKVN, DIM);
    }
    // 2) QK RMSNorm (in place, fp32)
    {
        dim3 grid(ROWS, 2);
        rmsnorm_kernel<<<grid, 256>>>(qkv, q_ln_w, k_ln_w);
    }
    // 3) Causal attention (fp32, validated) -> bf16 hi/lo split output
    {
        dim3 grid(SEQ / 64, BATCH * NHEAD);
        attn_kernel<<<grid, 256, 114688>>>(qkv, a_hi, a_lo);
    }
    // 4) Output projection (HMMA bf16x3, 2 CTAs/SM)
    {
        dim3 grid(DIM / GNT, ROWS / GMT);    // (16, 48)
        gemm_hmma_kernel<<<grid, 256, GSMEM_BYTES>>>(a_hi, a_lo, wo_hi, wo_lo, b_out, out, DIM, DIM);
    }
}